// round 1
// baseline (speedup 1.0000x reference)
#include <cuda_runtime.h>
#include <math.h>

// Shapes (fixed for this problem)
//  B=8, C=32, H=W=256.  irnn output channels = 4*C = 128.
#define HH 256
#define WW 256
#define HW 65536

// Scratch: ping-pong buffers as __device__ globals (no allocations allowed).
__device__ float g_a [8ULL *  32 * 65536];   //  64 MB : conv outputs (32ch)
__device__ float g_b4[8ULL * 128 * 65536];   // 256 MB : irnn outputs (128ch)

// ---------------------------------------------------------------------------
// 3x3 SAME conv, Cout=32, fp32.
//  - 16x16 pixel tile per CTA (256 threads, 1 thread = 1 pixel, 32 acc regs)
//  - input staged in smem in ci-chunks of 8 (with 1-px halo)
//  - weights staged in smem padded to 12 floats/(co,ci) so they can be read
//    as 3x LDS.128 broadcast per (co,ci) instead of 9 scalar LDS
//  - FUSE_OUT: fold relu + 1x1 conv + sigmoid into the epilogue
// ---------------------------------------------------------------------------
template<int CIN, bool FUSE_OUT>
__global__ __launch_bounds__(256)
void conv3x3_k(const float* __restrict__ in, const float* __restrict__ wgt,
               const float* __restrict__ wout, float* __restrict__ out)
{
    const int tx = threadIdx.x & 15;
    const int ty = threadIdx.x >> 4;
    const int w0 = blockIdx.x << 4;
    const int h0 = blockIdx.y << 4;
    const int b  = blockIdx.z;
    const int gw = w0 + tx, gh = h0 + ty;

    __shared__ __align__(16) float s_in[8 * 18 * 18];   // [ci][18][18]
    __shared__ __align__(16) float s_w [32 * 8 * 12];   // [co][ci][12] (9 used)

    float acc[32];
#pragma unroll
    for (int i = 0; i < 32; i++) acc[i] = 0.f;

    const float* inb = in + (size_t)b * CIN * HW;

    for (int ci0 = 0; ci0 < CIN; ci0 += 8) {
        // stage weights (broadcast-friendly, float4-aligned stride of 12)
        for (int idx = threadIdx.x; idx < 32 * 8 * 12; idx += 256) {
            int co  = idx / 96;
            int r   = idx - co * 96;
            int cic = r / 12;
            int k   = r - cic * 12;
            s_w[idx] = (k < 9) ? wgt[(co * CIN + ci0 + cic) * 9 + k] : 0.f;
        }
        // stage input tile with halo (zero pad at image border)
        for (int idx = threadIdx.x; idx < 8 * 324; idx += 256) {
            int cic = idx / 324;
            int rr  = idx - cic * 324;
            int r   = rr / 18;
            int cc  = rr - r * 18;
            int ih = h0 - 1 + r, iw = w0 - 1 + cc;
            float v = 0.f;
            if ((unsigned)ih < 256u && (unsigned)iw < 256u)
                v = inb[(size_t)(ci0 + cic) * HW + ih * 256 + iw];
            s_in[idx] = v;
        }
        __syncthreads();

#pragma unroll
        for (int cic = 0; cic < 8; cic++) {
            const float* t = &s_in[cic * 324 + ty * 18 + tx];
            float v0 = t[0],  v1 = t[1],  v2 = t[2];
            float v3 = t[18], v4 = t[19], v5 = t[20];
            float v6 = t[36], v7 = t[37], v8 = t[38];
            const float4* wq = (const float4*)&s_w[cic * 12];
#pragma unroll
            for (int co = 0; co < 32; co++) {
                float4 a  = wq[co * 24 + 0];
                float4 bq = wq[co * 24 + 1];
                float4 cq = wq[co * 24 + 2];
                acc[co] += v0 * a.x  + v1 * a.y  + v2 * a.z  + v3 * a.w
                         + v4 * bq.x + v5 * bq.y + v6 * bq.z + v7 * bq.w
                         + v8 * cq.x;
            }
        }
        __syncthreads();
    }

    if (FUSE_OUT) {
        float s = 0.f;
#pragma unroll
        for (int co = 0; co < 32; co++)
            s += fmaxf(acc[co], 0.f) * __ldg(&wout[co]);
        out[(size_t)b * HW + gh * 256 + gw] = 1.0f / (1.0f + expf(-s));
    } else {
#pragma unroll
        for (int co = 0; co < 32; co++)
            out[(size_t)(b * 32 + co) * HW + gh * 256 + gw] = acc[co];
    }
}

// ---------------------------------------------------------------------------
// IRNN scan along H (axis 2).  Thread = one (b, c, w) column; fully coalesced.
// out[t0] = x[t0] (raw), then h = relu(wc*h + bc + x[t]).
// Writes into the 128-channel irnn buffer at channel offset ch_off.
// ---------------------------------------------------------------------------
template<bool REV>
__global__ __launch_bounds__(256)
void scan_h(const float* __restrict__ in, float* __restrict__ out,
            const float* __restrict__ ws, const float* __restrict__ bs,
            int dir, int ch_off)
{
    int t = blockIdx.x * 256 + threadIdx.x;       // over B*C*W = 65536
    int wcoord = t & 255;
    int c = (t >> 8) & 31;
    int b = t >> 13;
    const float* ip = in  + (size_t)(b * 32  + c) * HW + wcoord;
    float*       op = out + (size_t)(b * 128 + ch_off + c) * HW + wcoord;
    float wc = ws[dir * 32 + c], bc = bs[dir * 32 + c];

    if (!REV) {
        float h = ip[0];
        op[0] = h;
        for (int y = 1; y < 256; y++) {
            h = fmaxf(wc * h + bc + ip[y * 256], 0.f);
            op[y * 256] = h;
        }
    } else {
        float h = ip[255 * 256];
        op[255 * 256] = h;
        for (int y = 254; y >= 0; y--) {
            h = fmaxf(wc * h + bc + ip[y * 256], 0.f);
            op[y * 256] = h;
        }
    }
}

// ---------------------------------------------------------------------------
// IRNN scan along W (axis 3).  Block handles 32 rows of one (b,c) plane.
// Coalesced global I/O via a 32x33 smem transpose tile; warp 0 does the
// serial recurrence (one thread per row, state carried across 32-col chunks).
// ---------------------------------------------------------------------------
template<bool REV>
__global__ __launch_bounds__(256)
void scan_w(const float* __restrict__ in, float* __restrict__ out,
            const float* __restrict__ ws, const float* __restrict__ bs,
            int dir, int ch_off)
{
    __shared__ float tile[32][33];
    int R0 = blockIdx.x * 32;                 // flat row index over (b, c, h)
    int c  = (R0 >> 8) & 31;
    int b  = R0 >> 13;
    int h0 = R0 & 255;
    float wc = ws[dir * 32 + c], bc = bs[dir * 32 + c];

    const float* ip = in + (size_t)R0 * 256;
    float* op = out + ((size_t)(b * 128 + ch_off + c) * 256 + h0) * 256;

    int lr   = threadIdx.x >> 5;   // 0..7
    int lcol = threadIdx.x & 31;

    float hstate = 0.f;
    for (int ch = 0; ch < 8; ch++) {
        int wc0 = REV ? (224 - ch * 32) : ch * 32;
#pragma unroll
        for (int i = 0; i < 4; i++) {
            int r = lr + i * 8;
            tile[r][lcol] = ip[r * 256 + wc0 + lcol];
        }
        __syncthreads();
        if (threadIdx.x < 32) {
            int r = threadIdx.x;
            float h = hstate;
            if (!REV) {
                for (int j = 0; j < 32; j++) {
                    float val = tile[r][j];
                    h = (ch == 0 && j == 0) ? val : fmaxf(wc * h + bc + val, 0.f);
                    tile[r][j] = h;
                }
            } else {
                for (int j = 31; j >= 0; j--) {
                    float val = tile[r][j];
                    h = (ch == 0 && j == 31) ? val : fmaxf(wc * h + bc + val, 0.f);
                    tile[r][j] = h;
                }
            }
            hstate = h;
        }
        __syncthreads();
#pragma unroll
        for (int i = 0; i < 4; i++) {
            int r = lr + i * 8;
            op[r * 256 + wc0 + lcol] = tile[r][lcol];
        }
        __syncthreads();
    }
}

// ---------------------------------------------------------------------------
// Launch: conv1 -> irnn1 (4 scans) -> conv2 -> irnn2 (4 scans) ->
//         conv3 fused with relu + 1x1 conv + sigmoid.
// Channel concat order: up(0), right(32), down(64), left(96);
// irnn weight row order: 0=up, 1=right, 2=down, 3=left.
// ---------------------------------------------------------------------------
extern "C" void kernel_launch(void* const* d_in, const int* in_sizes, int n_in,
                              void* d_out, int out_size)
{
    const float* x   = (const float*)d_in[0];
    const float* w1  = (const float*)d_in[1];
    const float* w2  = (const float*)d_in[2];
    const float* w3  = (const float*)d_in[3];
    const float* wo  = (const float*)d_in[4];
    const float* i1w = (const float*)d_in[5];
    const float* i1b = (const float*)d_in[6];
    const float* i2w = (const float*)d_in[7];
    const float* i2b = (const float*)d_in[8];
    float* outp = (float*)d_out;

    float *ga, *gb;
    cudaGetSymbolAddress((void**)&ga, g_a);
    cudaGetSymbolAddress((void**)&gb, g_b4);

    dim3 cg(16, 16, 8);

    conv3x3_k<32,  false><<<cg, 256>>>(x,  w1, nullptr, ga);

    scan_h<true ><<<256,  256>>>(ga, gb, i1w, i1b, 0,  0);   // up
    scan_w<false><<<2048, 256>>>(ga, gb, i1w, i1b, 1, 32);   // right
    scan_h<false><<<256,  256>>>(ga, gb, i1w, i1b, 2, 64);   // down
    scan_w<true ><<<2048, 256>>>(ga, gb, i1w, i1b, 3, 96);   // left

    conv3x3_k<128, false><<<cg, 256>>>(gb, w2, nullptr, ga);

    scan_h<true ><<<256,  256>>>(ga, gb, i2w, i2b, 0,  0);
    scan_w<false><<<2048, 256>>>(ga, gb, i2w, i2b, 1, 32);
    scan_h<false><<<256,  256>>>(ga, gb, i2w, i2b, 2, 64);
    scan_w<true ><<<2048, 256>>>(ga, gb, i2w, i2b, 3, 96);

    conv3x3_k<128, true ><<<cg, 256>>>(gb, w3, wo, outp);
}